// round 1
// baseline (speedup 1.0000x reference)
#include <cuda_runtime.h>
#include <cuda_bf16.h>

// Problem shapes (fixed by setup_inputs):
//   feat_pos: (B, D)   = (256, 100)   float32
//   feat_neg: (B, C, D)= (256, 4096, 100) float32
//   feat_lan: (B, D)   = (256, 100)   float32
// Output: scalar float32 loss = mean((pos-lan)^2) + mean(relu(0.1 - mean_d((pos-neg)^2)))

#define B_DIM 256
#define C_DIM 4096
#define D_DIM 100
#define MARGIN 0.1f

// Scratch accumulators (device globals — no allocation). Re-initialized by
// k_init_loss1 on every launch/replay, so the graph is deterministic.
__device__ float g_acc1;   // sum over (b,d) of (pos-lan)^2
__device__ float g_acc2;   // sum over (b,c) of relu(MARGIN - d2)

// ---------------------------------------------------------------------------
// Kernel 1: loss1 partial (tiny: 25600 elements) + zero the loss2 accumulator.
// Single block of 256 threads.
// ---------------------------------------------------------------------------
__global__ void k_init_loss1(const float* __restrict__ pos,
                             const float* __restrict__ lan) {
    __shared__ float red[256];
    float s = 0.f;
    for (int i = threadIdx.x; i < B_DIM * D_DIM; i += 256) {
        float d = pos[i] - lan[i];
        s += d * d;
    }
    red[threadIdx.x] = s;
    __syncthreads();
    #pragma unroll
    for (int o = 128; o > 0; o >>= 1) {
        if (threadIdx.x < o) red[threadIdx.x] += red[threadIdx.x + o];
        __syncthreads();
    }
    if (threadIdx.x == 0) {
        g_acc1 = red[0];
        g_acc2 = 0.f;
    }
}

// ---------------------------------------------------------------------------
// Kernel 2: loss2. Warp-per-row over the (B*C) rows of feat_neg.
//   grid.x = B * CHUNKS (CHUNKS=16) = 4096 blocks, 256 threads (8 warps).
//   Each block owns one b (pos row cached in registers) and 256 c-rows;
//   each warp streams 32 consecutive rows (400 contiguous bytes per row,
//   LDG.128 from lanes 0..24 -> fully coalesced HBM streaming).
// ---------------------------------------------------------------------------
__global__ void __launch_bounds__(256)
k_loss2(const float* __restrict__ pos, const float* __restrict__ neg) {
    const int lane  = threadIdx.x & 31;
    const int warp  = threadIdx.x >> 5;
    const int b     = blockIdx.x >> 4;        // / CHUNKS
    const int chunk = blockIdx.x & 15;        // % CHUNKS
    const int c0    = chunk * 256 + warp * 32;

    // Cache this block's pos row slice in registers (lanes 0..24 active).
    float4 p = make_float4(0.f, 0.f, 0.f, 0.f);
    if (lane < 25)
        p = *reinterpret_cast<const float4*>(pos + b * D_DIM + lane * 4);

    const float* base =
        neg + ((size_t)b * C_DIM + (size_t)c0) * D_DIM;

    float acc = 0.f;
    #pragma unroll 4
    for (int r = 0; r < 32; ++r) {
        float partial = 0.f;
        if (lane < 25) {
            float4 n = *reinterpret_cast<const float4*>(
                base + (size_t)r * D_DIM + lane * 4);
            float dx = p.x - n.x, dy = p.y - n.y;
            float dz = p.z - n.z, dw = p.w - n.w;
            partial = dx * dx + dy * dy + dz * dz + dw * dw;
        }
        // Full-warp butterfly reduce (lanes 25..31 contribute 0).
        #pragma unroll
        for (int o = 16; o > 0; o >>= 1)
            partial += __shfl_xor_sync(0xffffffffu, partial, o);
        // d2 = partial / D; hinge
        acc += fmaxf(0.f, MARGIN - partial * (1.0f / (float)D_DIM));
    }
    if (lane == 0) atomicAdd(&g_acc2, acc);
}

// ---------------------------------------------------------------------------
// Kernel 3: finalize -> scalar output.
// ---------------------------------------------------------------------------
__global__ void k_final(float* __restrict__ out) {
    out[0] = g_acc1 * (1.0f / (float)(B_DIM * D_DIM))
           + g_acc2 * (1.0f / (float)(B_DIM * C_DIM));  // LAMDA = 1
}

extern "C" void kernel_launch(void* const* d_in, const int* in_sizes, int n_in,
                              void* d_out, int out_size) {
    const float* feat_pos = (const float*)d_in[0];
    const float* feat_neg = (const float*)d_in[1];
    const float* feat_lan = (const float*)d_in[2];
    float* out = (float*)d_out;

    k_init_loss1<<<1, 256>>>(feat_pos, feat_lan);
    k_loss2<<<B_DIM * 16, 256>>>(feat_pos, feat_neg);
    k_final<<<1, 1>>>(out);
}

// round 2
// speedup vs baseline: 1.1965x; 1.1965x over previous
#include <cuda_runtime.h>
#include <cuda_bf16.h>

// Shapes (fixed): pos (256,100) f32, neg (256,4096,100) f32, lan (256,100) f32.
// out = mean((pos-lan)^2) + mean(relu(0.1 - mean_d((pos-neg)^2)))

#define B_DIM   256
#define C_DIM   4096
#define D_DIM   100
#define MARGIN  0.1f
#define INV_D   (1.0f / 100.0f)
#define INV_BC  (1.0f / (256.0f * 4096.0f))
#define INV_BD  (1.0f / (256.0f * 100.0f))
#define GRID_X  (B_DIM * 16)   // 4096 blocks

// Device-global scratch (no allocations). Zero-initialized at module load;
// the last-arriving block resets both to 0 each call, so every graph replay
// sees the same initial state -> deterministic.
__device__ float    g_acc;
__device__ unsigned g_count;

// ---------------------------------------------------------------------------
// Single fused kernel.
//   grid = 4096 (16 chunks per b), block = 256 (8 warps).
//   Each warp streams 32 consecutive c-rows (400 B contiguous each, LDG.128
//   from lanes 0..24), butterfly-reduces per row, applies the hinge.
//   chunk==0 blocks additionally compute b's loss1 slice (100 elements).
//   One atomicAdd per block; last block writes the scalar output and resets
//   the accumulators for the next replay.
// ---------------------------------------------------------------------------
__global__ void __launch_bounds__(256)
k_fused(const float* __restrict__ pos,
        const float* __restrict__ neg,
        const float* __restrict__ lan,
        float* __restrict__ out) {
    const int lane  = threadIdx.x & 31;
    const int warp  = threadIdx.x >> 5;
    const int b     = blockIdx.x >> 4;    // / 16
    const int chunk = blockIdx.x & 15;    // % 16
    const int c0    = chunk * 256 + warp * 32;

    // pos row slice cached in registers (lanes 0..24 hold 25 float4 = 100 f32)
    float4 p = make_float4(0.f, 0.f, 0.f, 0.f);
    if (lane < 25)
        p = *reinterpret_cast<const float4*>(pos + b * D_DIM + lane * 4);

    const float* base = neg + ((size_t)b * C_DIM + (size_t)c0) * D_DIM;

    // ---- loss2: 32 rows per warp -------------------------------------------
    float acc2 = 0.f;
    #pragma unroll 8
    for (int r = 0; r < 32; ++r) {
        float partial = 0.f;
        if (lane < 25) {
            float4 n = *reinterpret_cast<const float4*>(
                base + (size_t)r * D_DIM + lane * 4);
            float dx = p.x - n.x, dy = p.y - n.y;
            float dz = p.z - n.z, dw = p.w - n.w;
            partial = dx * dx + dy * dy + dz * dz + dw * dw;
        }
        #pragma unroll
        for (int o = 16; o > 0; o >>= 1)
            partial += __shfl_xor_sync(0xffffffffu, partial, o);
        acc2 += fmaxf(0.f, MARGIN - partial * INV_D);
    }

    // ---- loss1: chunk-0 blocks handle their b's 100 elements ---------------
    float l1 = 0.f;
    if (chunk == 0 && threadIdx.x < D_DIM) {
        float d = pos[b * D_DIM + threadIdx.x] - lan[b * D_DIM + threadIdx.x];
        l1 = d * d;
    }
    #pragma unroll
    for (int o = 16; o > 0; o >>= 1)
        l1 += __shfl_xor_sync(0xffffffffu, l1, o);

    // ---- block reduce -> one atomic per block -------------------------------
    __shared__ float s2[8], s1[8];
    if (lane == 0) { s2[warp] = acc2; s1[warp] = l1; }
    __syncthreads();

    if (threadIdx.x == 0) {
        float t2 = 0.f, t1 = 0.f;
        #pragma unroll
        for (int w = 0; w < 8; ++w) { t2 += s2[w]; t1 += s1[w]; }
        atomicAdd(&g_acc, t2 * INV_BC + t1 * INV_BD);   // LAMDA = 1
        __threadfence();
        unsigned done = atomicAdd(&g_count, 1u);
        if (done == GRID_X - 1) {
            // All other blocks fenced their g_acc add before bumping g_count,
            // so an atomic read here sees the complete sum.
            float total = atomicAdd(&g_acc, 0.0f);
            out[0] = total;
            // Reset for the next graph replay (stream-ordered before it).
            g_acc   = 0.f;
            g_count = 0u;
        }
    }
}

extern "C" void kernel_launch(void* const* d_in, const int* in_sizes, int n_in,
                              void* d_out, int out_size) {
    const float* feat_pos = (const float*)d_in[0];
    const float* feat_neg = (const float*)d_in[1];
    const float* feat_lan = (const float*)d_in[2];
    float* out = (float*)d_out;

    k_fused<<<GRID_X, 256>>>(feat_pos, feat_neg, feat_lan, out);
}

// round 3
// speedup vs baseline: 1.4768x; 1.2343x over previous
#include <cuda_runtime.h>
#include <cuda_bf16.h>

// Shapes (fixed): pos (256,100) f32, neg (256,4096,100) f32, lan (256,100) f32.
// out = mean((pos-lan)^2) + mean(relu(0.1 - mean_d((pos-neg)^2)))

#define B_DIM   256
#define C_DIM   4096
#define D_DIM   100
#define MARGIN  0.1f
#define INV_D   (1.0f / 100.0f)
#define INV_BC  (1.0f / (256.0f * 4096.0f))
#define INV_BD  (1.0f / (256.0f * 100.0f))
#define GRID_X  (B_DIM * 16)   // 4096 blocks

// Device-global scratch (no allocations). Last block resets both each call,
// so every graph replay sees identical initial state.
__device__ float    g_acc;
__device__ unsigned g_count;

__device__ __forceinline__ float row_partial(float4 p, float4 n) {
    float dx = p.x - n.x, dy = p.y - n.y;
    float dz = p.z - n.z, dw = p.w - n.w;
    return dx * dx + dy * dy + dz * dz + dw * dw;
}

// ---------------------------------------------------------------------------
// Single fused kernel. grid = 4096 (16 chunks per b), block = 256 (8 warps).
// Each warp streams 32 c-rows; rows are reduced 4-at-a-time with a combined
// butterfly (9 shfls / 4 rows instead of 20) to relieve MIO pressure.
// ---------------------------------------------------------------------------
__global__ void __launch_bounds__(256)
k_fused(const float* __restrict__ pos,
        const float* __restrict__ neg,
        const float* __restrict__ lan,
        float* __restrict__ out) {
    const int lane  = threadIdx.x & 31;
    const int warp  = threadIdx.x >> 5;
    const int b     = blockIdx.x >> 4;    // / 16
    const int chunk = blockIdx.x & 15;    // % 16
    const int c0    = chunk * 256 + warp * 32;
    const bool act  = (lane < 25);        // 25 float4 = 100 floats per row
    const bool hi16 = (lane & 16) != 0;
    const bool hi8  = (lane & 8) != 0;

    float4 p = make_float4(0.f, 0.f, 0.f, 0.f);
    if (act) p = *reinterpret_cast<const float4*>(pos + b * D_DIM + lane * 4);

    const float* base = neg + ((size_t)b * C_DIM + (size_t)c0) * D_DIM;

    float acc2 = 0.f;
    #pragma unroll 2
    for (int it = 0; it < 8; ++it) {
        const float* rb = base + (size_t)it * 4 * D_DIM + lane * 4;

        // 4 independent loads up-front (MLP).
        float4 n0, n1, n2, n3;
        if (act) {
            n0 = *reinterpret_cast<const float4*>(rb + 0 * D_DIM);
            n1 = *reinterpret_cast<const float4*>(rb + 1 * D_DIM);
            n2 = *reinterpret_cast<const float4*>(rb + 2 * D_DIM);
            n3 = *reinterpret_cast<const float4*>(rb + 3 * D_DIM);
        }

        float pa = 0.f, pb = 0.f, pc = 0.f, pd = 0.f;
        if (act) {
            pa = row_partial(p, n0);
            pb = row_partial(p, n1);
            pc = row_partial(p, n2);
            pd = row_partial(p, n3);
        }

        // Combined butterfly: 9 shfls reduce all 4 rows.
        // Stage 1 (xor 16): fold 32->16 lanes, pack rows a|b and c|d.
        float ua = __shfl_xor_sync(0xffffffffu, pa, 16);
        float ub = __shfl_xor_sync(0xffffffffu, pb, 16);
        float uc = __shfl_xor_sync(0xffffffffu, pc, 16);
        float ud = __shfl_xor_sync(0xffffffffu, pd, 16);
        float e = hi16 ? (pb + ub) : (pa + ua);   // lanes 0-15: a, 16-31: b
        float f = hi16 ? (pd + ud) : (pc + uc);   // lanes 0-15: c, 16-31: d

        // Stage 2 (xor 8): fold 16->8, pack all four rows into one reg.
        float ue = __shfl_xor_sync(0xffffffffu, e, 8);
        float uf = __shfl_xor_sync(0xffffffffu, f, 8);
        float g = hi8 ? (f + uf) : (e + ue);      // 0-7:a, 8-15:c, 16-23:b, 24-31:d

        // Stage 3: finish within 8-lane groups.
        g += __shfl_xor_sync(0xffffffffu, g, 4);
        g += __shfl_xor_sync(0xffffffffu, g, 2);
        g += __shfl_xor_sync(0xffffffffu, g, 1);

        // Lanes 0,8,16,24 hold the 4 row sums -> hinge (predicated).
        if ((lane & 7) == 0)
            acc2 += fmaxf(0.f, fmaf(g, -INV_D, MARGIN));
    }

    // ---- loss1: chunk-0 blocks handle their b's 100 elements ---------------
    float l1 = 0.f;
    if (chunk == 0 && threadIdx.x < D_DIM) {
        float d = pos[b * D_DIM + threadIdx.x] - lan[b * D_DIM + threadIdx.x];
        l1 = d * d;
    }

    // ---- warp reduce (once per warp) then block reduce ----------------------
    float v = acc2 * INV_BC + l1 * INV_BD;        // LAMDA = 1
    #pragma unroll
    for (int o = 16; o > 0; o >>= 1)
        v += __shfl_xor_sync(0xffffffffu, v, o);

    __shared__ float sred[8];
    if (lane == 0) sred[warp] = v;
    __syncthreads();

    if (threadIdx.x == 0) {
        float t = 0.f;
        #pragma unroll
        for (int w = 0; w < 8; ++w) t += sred[w];
        atomicAdd(&g_acc, t);
        __threadfence();
        unsigned done = atomicAdd(&g_count, 1u);
        if (done == GRID_X - 1) {
            float total = atomicAdd(&g_acc, 0.0f); // atomic read: complete sum
            out[0] = total;
            g_acc   = 0.f;                          // reset for next replay
            g_count = 0u;
        }
    }
}

extern "C" void kernel_launch(void* const* d_in, const int* in_sizes, int n_in,
                              void* d_out, int out_size) {
    const float* feat_pos = (const float*)d_in[0];
    const float* feat_neg = (const float*)d_in[1];
    const float* feat_lan = (const float*)d_in[2];
    float* out = (float*)d_out;

    k_fused<<<GRID_X, 256>>>(feat_pos, feat_neg, feat_lan, out);
}